// round 14
// baseline (speedup 1.0000x reference)
#include <cuda_runtime.h>
#include <cuda_bf16.h>
#include <math.h>

#define NNODES 50000
#define NEDGES 800000
#define IN_DIM 128
#define HID 96
#define PROJ 64
#define BN_EPS 1e-5f

// ---------------- scratch (device globals; statically zero-initialized) ----
__device__ __align__(16) float g_xws[NNODES * HID];   // GEMM outputs
__device__ __align__(16) float g_h[NNODES * HID];     // pre-BN activations
__device__ float g_dinv[NNODES];
__device__ float g_stat1[2 * HID];   // BN1 stats (sum | sumsq); scan_k zeroes
__device__ float g_stat2[2 * HID];   // BN2 stats
__device__ float g_stat3[2 * HID];   // projector BN stats
__device__ int   g_cnt[NNODES];      // zeroed statically; scan_k re-zeroes
__device__ int   g_rowptr[NNODES + 1];
__device__ int   g_cursor[NNODES];
__device__ int   g_csr[NEDGES];

// ---------------- CSR build (edge_index is int32: jnp x64 disabled) --------
__global__ void count_k(const int* __restrict__ ei) {
    int e = blockIdx.x * blockDim.x + threadIdx.x;
    if (e < NEDGES) atomicAdd(&g_cnt[ei[NEDGES + e]], 1);
}

// coalesced tiled exclusive scan; computes dinv; resets g_cnt; zeroes stats
__global__ void __launch_bounds__(1024) scan_k() {
    __shared__ int wsum[32];
    int t = threadIdx.x, lane = t & 31, w = t >> 5;
    if (t < 2 * HID) { g_stat1[t] = 0.f; g_stat2[t] = 0.f; g_stat3[t] = 0.f; }
    int carry = 0;
    for (int t0 = 0; t0 < NNODES; t0 += 1024) {
        int i = t0 + t;
        int v = (i < NNODES) ? g_cnt[i] : 0;
        if (i < NNODES) {
            g_dinv[i] = rsqrtf((float)(v + 1));
            g_cnt[i] = 0;
        }
        int x = v;
#pragma unroll
        for (int o = 1; o < 32; o <<= 1) {
            int y = __shfl_up_sync(0xffffffff, x, o);
            if (lane >= o) x += y;
        }
        if (lane == 31) wsum[w] = x;
        __syncthreads();
        if (w == 0) {
            int s = wsum[lane];
#pragma unroll
            for (int o = 1; o < 32; o <<= 1) {
                int y = __shfl_up_sync(0xffffffff, s, o);
                if (lane >= o) s += y;
            }
            wsum[lane] = s;
        }
        __syncthreads();
        int excl = x - v + (w > 0 ? wsum[w - 1] : 0) + carry;
        if (i < NNODES) { g_rowptr[i] = excl; g_cursor[i] = excl; }
        carry += wsum[31];
        __syncthreads();
    }
    if (t == 0) g_rowptr[NNODES] = carry;
}

__global__ void fill_k(const int* __restrict__ ei) {
    int e = blockIdx.x * blockDim.x + threadIdx.x;
    if (e < NEDGES) {
        int src = ei[e];
        int dst = ei[NEDGES + e];
        int pos = atomicAdd(&g_cursor[dst], 1);
        g_csr[pos] = src;
    }
}

// ------------- bf16-split tensor-core GEMM (3x m16n8k16) -------------------
// Double-buffered software pipeline: stage tile k+1 while MMAs consume tile k.
#define GBM 128
#define GBK 32
#define AKW (GBK / 2)
#define AS_STRIDE 20
#define ABUF (GBM * AS_STRIDE)          // 2560 words per A half-buffer

#define MMA_BF16(d, a0, a1, a2, a3, b0, b1)                                   \
    asm volatile(                                                             \
        "mma.sync.aligned.m16n8k16.row.col.f32.bf16.bf16.f32 "                \
        "{%0,%1,%2,%3},{%4,%5,%6,%7},{%8,%9},{%0,%1,%2,%3};"                  \
        : "+f"(d[0]), "+f"(d[1]), "+f"(d[2]), "+f"(d[3])                      \
        : "r"(a0), "r"(a1), "r"(a2), "r"(a3), "r"(b0), "r"(b1))

__device__ __forceinline__ void split2(float v0, float v1,
                                       unsigned& hw, unsigned& lw) {
    __nv_bfloat16 h0 = __float2bfloat16(v0);
    __nv_bfloat16 h1 = __float2bfloat16(v1);
    __nv_bfloat16 l0 = __float2bfloat16(v0 - __bfloat162float(h0));
    __nv_bfloat16 l1 = __float2bfloat16(v1 - __bfloat162float(h1));
    __nv_bfloat162 hh = __halves2bfloat162(h0, h1);
    __nv_bfloat162 ll = __halves2bfloat162(l0, l1);
    hw = *reinterpret_cast<unsigned*>(&hh);
    lw = *reinterpret_cast<unsigned*>(&ll);
}

extern __shared__ unsigned dynsmem[];

template <int GBN, bool NORM, bool DO_STATS>
__global__ void __launch_bounds__(256, 2) tgemm_k(
    const float* __restrict__ A, const float* __restrict__ B,
    const float* __restrict__ bias, float* __restrict__ C,
    int M, int K,
    const float* __restrict__ gam, const float* __restrict__ bet,
    const float* __restrict__ stats,
    const float* __restrict__ rowscale, float* __restrict__ outstats)
{
    const int BS_STRIDE = GBN + 8;
    const int NJ = GBN / 16;
    const int BBUF = AKW * BS_STRIDE;

    // dynamic smem layout: Ahi[2] | Alo[2] | Bhi[2] | Blo[2]
    unsigned* AhiP = dynsmem;                 // [2][ABUF]
    unsigned* AloP = dynsmem + 2 * ABUF;      // [2][ABUF]
    unsigned* BhiP = dynsmem + 4 * ABUF;      // [2][BBUF]
    unsigned* BloP = dynsmem + 4 * ABUF + 2 * BBUF;

    __shared__ float tas[HID], tcs[HID];
    __shared__ float ssum[GBN], ssq[GBN];
    __shared__ float rowsq[GBM];

    int m0 = blockIdx.x * GBM;
    int tid = threadIdx.x;
    int wid = tid >> 5, lane = tid & 31;
    int g = lane >> 2, t4 = lane & 3;
    int wrow = wid >> 1;
    int wcol = wid & 1;
    int rbase = wrow * 32;
    int cbase = wcol * (GBN / 2);

    bool hasAff = (gam != nullptr);
    if (hasAff && tid < HID) {
        float mean = stats[tid] * (1.0f / NNODES);
        float var = stats[HID + tid] * (1.0f / NNODES) - mean * mean;
        float a = gam[tid] * rsqrtf(var + BN_EPS);
        tas[tid] = a;
        tcs[tid] = bet[tid] - a * mean;
    }
    if (DO_STATS && tid < GBN) { ssum[tid] = 0.0f; ssq[tid] = 0.0f; }
    if (NORM && tid < GBM) rowsq[tid] = 0.0f;
    // REQUIRED: stage() below reads tas/tcs — publish the affine init first.
    __syncthreads();

    // staging of one (A,B) tile pair at K-offset k0 into buffer b
    auto stage = [&](int b, int k0) {
        unsigned* Ahi = AhiP + b * ABUF;
        unsigned* Alo = AloP + b * ABUF;
        unsigned* Bhi = BhiP + b * BBUF;
        unsigned* Blo = BloP + b * BBUF;
#pragma unroll
        for (int l = 0; l < 8; l++) {
            int idx = l * 256 + tid;
            int row = idx >> 4;
            int kw = idx & 15;
            int m = m0 + row;
            int kk = k0 + 2 * kw;
            float v0 = 0.0f, v1 = 0.0f;
            if (m < M) {
                float2 u = *(const float2*)(A + (long)m * K + kk);
                v0 = u.x; v1 = u.y;
                if (hasAff) {
                    v0 = fmaxf(fmaf(tas[kk], v0, tcs[kk]), 0.0f);
                    v1 = fmaxf(fmaf(tas[kk + 1], v1, tcs[kk + 1]), 0.0f);
                }
            }
            unsigned hw, lw;
            split2(v0, v1, hw, lw);
            Ahi[row * AS_STRIDE + kw] = hw;
            Alo[row * AS_STRIDE + kw] = lw;
        }
#pragma unroll
        for (int l = 0; l < NJ; l++) {
            int idx = l * 256 + tid;
            int kw = idx / GBN;
            int n = idx - kw * GBN;
            int kk = k0 + 2 * kw;
            float u0 = B[(long)kk * GBN + n];
            float u1 = B[(long)(kk + 1) * GBN + n];
            unsigned hw, lw;
            split2(u0, u1, hw, lw);
            Bhi[kw * BS_STRIDE + n] = hw;
            Blo[kw * BS_STRIDE + n] = lw;
        }
    };

    float acc[2][6][4];
#pragma unroll
    for (int i = 0; i < 2; i++)
#pragma unroll
        for (int j = 0; j < 6; j++)
#pragma unroll
            for (int q = 0; q < 4; q++) acc[i][j][q] = 0.0f;

    // prologue: stage tile 0
    stage(0, 0);
    __syncthreads();

    int nIter = K / GBK;
    for (int it = 0; it < nIter; it++) {
        int cur = it & 1;
        // prefetch next tile into the other buffer (overlaps with MMAs below)
        if (it + 1 < nIter) stage(cur ^ 1, (it + 1) * GBK);

        unsigned* Ahi = AhiP + cur * ABUF;
        unsigned* Alo = AloP + cur * ABUF;
        unsigned* Bhi = BhiP + cur * BBUF;
        unsigned* Blo = BloP + cur * BBUF;

#pragma unroll
        for (int kg = 0; kg < 2; kg++) {
            int kwb = kg * 8;
            unsigned ahi[2][4], alo[2][4];
#pragma unroll
            for (int i = 0; i < 2; i++) {
                int r0 = (rbase + i * 16 + g) * AS_STRIDE + kwb;
                int r1 = (rbase + i * 16 + 8 + g) * AS_STRIDE + kwb;
                ahi[i][0] = Ahi[r0 + t4];
                ahi[i][1] = Ahi[r1 + t4];
                ahi[i][2] = Ahi[r0 + 4 + t4];
                ahi[i][3] = Ahi[r1 + 4 + t4];
                alo[i][0] = Alo[r0 + t4];
                alo[i][1] = Alo[r1 + t4];
                alo[i][2] = Alo[r0 + 4 + t4];
                alo[i][3] = Alo[r1 + 4 + t4];
            }
            unsigned bhi[6][2], blo[6][2];
#pragma unroll
            for (int j = 0; j < NJ; j++) {
                int n = cbase + j * 8 + g;
                bhi[j][0] = Bhi[(kwb + t4) * BS_STRIDE + n];
                bhi[j][1] = Bhi[(kwb + 4 + t4) * BS_STRIDE + n];
                blo[j][0] = Blo[(kwb + t4) * BS_STRIDE + n];
                blo[j][1] = Blo[(kwb + 4 + t4) * BS_STRIDE + n];
            }
#pragma unroll
            for (int i = 0; i < 2; i++)
#pragma unroll
                for (int j = 0; j < NJ; j++) {
                    float* d = acc[i][j];
                    MMA_BF16(d, ahi[i][0], ahi[i][1], ahi[i][2], ahi[i][3],
                             blo[j][0], blo[j][1]);
                    MMA_BF16(d, alo[i][0], alo[i][1], alo[i][2], alo[i][3],
                             bhi[j][0], bhi[j][1]);
                    MMA_BF16(d, ahi[i][0], ahi[i][1], ahi[i][2], ahi[i][3],
                             bhi[j][0], bhi[j][1]);
                }
        }
        // one sync per iteration: publishes buffer cur^1 for the next
        // iteration AND retires all reads of cur before it is re-staged.
        __syncthreads();
    }

    // ---- epilogue ----
    if (NORM) {
#pragma unroll
        for (int i = 0; i < 2; i++) {
#pragma unroll
            for (int h = 0; h < 2; h++) {
                int rloc = rbase + i * 16 + g + h * 8;
                int row = m0 + rloc;
                float lsq = 0.0f;
#pragma unroll
                for (int j = 0; j < NJ; j++) {
                    int col = cbase + j * 8 + t4 * 2;
                    float v0 = acc[i][j][h * 2 + 0] + bias[col];
                    float v1 = acc[i][j][h * 2 + 1] + bias[col + 1];
                    acc[i][j][h * 2 + 0] = v0;
                    acc[i][j][h * 2 + 1] = v1;
                    lsq += v0 * v0 + v1 * v1;
                }
                if (row < M) atomicAdd(&rowsq[rloc], lsq);
            }
        }
        __syncthreads();
#pragma unroll
        for (int i = 0; i < 2; i++) {
#pragma unroll
            for (int h = 0; h < 2; h++) {
                int rloc = rbase + i * 16 + g + h * 8;
                int row = m0 + rloc;
                if (row < M) {
                    float inv = 1.0f / fmaxf(sqrtf(rowsq[rloc]), 1e-12f);
#pragma unroll
                    for (int j = 0; j < NJ; j++) {
                        int col = cbase + j * 8 + t4 * 2;
                        float2 o;
                        o.x = acc[i][j][h * 2 + 0] * inv;
                        o.y = acc[i][j][h * 2 + 1] * inv;
                        *(float2*)(C + (long)row * GBN + col) = o;
                    }
                }
            }
        }
    } else {
#pragma unroll
        for (int j = 0; j < NJ; j++) {
            int col = cbase + j * 8 + t4 * 2;
            float ls0 = 0.f, ls1 = 0.f, lq0 = 0.f, lq1 = 0.f;
#pragma unroll
            for (int i = 0; i < 2; i++) {
#pragma unroll
                for (int h = 0; h < 2; h++) {
                    int row = m0 + rbase + i * 16 + g + h * 8;
                    if (row < M) {
                        float rs = rowscale ? rowscale[row] : 1.0f;
                        float v0 = acc[i][j][h * 2 + 0];
                        float v1 = acc[i][j][h * 2 + 1];
                        if (bias) { v0 += bias[col]; v1 += bias[col + 1]; }
                        v0 *= rs; v1 *= rs;
                        float2 o; o.x = v0; o.y = v1;
                        *(float2*)(C + (long)row * GBN + col) = o;
                        if (DO_STATS) {
                            ls0 += v0; ls1 += v1;
                            lq0 += v0 * v0; lq1 += v1 * v1;
                        }
                    }
                }
            }
            if (DO_STATS) {
                atomicAdd(&ssum[col], ls0);
                atomicAdd(&ssum[col + 1], ls1);
                atomicAdd(&ssq[col], lq0);
                atomicAdd(&ssq[col + 1], lq1);
            }
        }
        if (DO_STATS) {
            __syncthreads();
            if (tid < GBN) {
                atomicAdd(&outstats[tid], ssum[tid]);
                atomicAdd(&outstats[GBN + tid], ssq[tid]);
            }
        }
    }
}

// ------- fused aggregation + GCN epilogue + BN stats (warp per row) --------
template <bool SRCSCALE>
__global__ void __launch_bounds__(256) agg_k(const float* __restrict__ bias,
                                             float* __restrict__ stats) {
    int gwarp = (blockIdx.x * blockDim.x + threadIdx.x) >> 5;
    int nwarps = (gridDim.x * blockDim.x) >> 5;
    int lane = threadIdx.x & 31;

    const float b0 = bias[lane];
    const float b1 = bias[lane + 32];
    const float b2 = bias[lane + 64];

    float s0 = 0.f, s1 = 0.f, s2 = 0.f;
    float q0 = 0.f, q1 = 0.f, q2 = 0.f;

    for (int row = gwarp; row < NNODES; row += nwarps) {
        int st = g_rowptr[row];
        int en = g_rowptr[row + 1];
        float a0 = 0.f, a1 = 0.f, a2 = 0.f;

        for (int base = st; base < en; base += 32) {
            int idx = base + lane;
            int s = (idx < en) ? g_csr[idx] : 0;
            float dsc = SRCSCALE ? g_dinv[s] : 1.0f;
            int cnt = min(32, en - base);
#pragma unroll 4
            for (int j = 0; j < cnt; j++) {
                int sj = __shfl_sync(0xffffffff, s, j);
                const float* xr = g_xws + (long)sj * HID;
                if (SRCSCALE) {
                    float dj = __shfl_sync(0xffffffff, dsc, j);
                    a0 = fmaf(dj, xr[lane],      a0);
                    a1 = fmaf(dj, xr[lane + 32], a1);
                    a2 = fmaf(dj, xr[lane + 64], a2);
                } else {
                    a0 += xr[lane];
                    a1 += xr[lane + 32];
                    a2 += xr[lane + 64];
                }
            }
        }
        float di = g_dinv[row];
        const float* xs = g_xws + (long)row * HID;
        float selfscale = SRCSCALE ? di : 1.0f;
        float v0 = fmaf(di, fmaf(selfscale, xs[lane],      a0), b0);
        float v1 = fmaf(di, fmaf(selfscale, xs[lane + 32], a1), b1);
        float v2 = fmaf(di, fmaf(selfscale, xs[lane + 64], a2), b2);
        float* hr = g_h + (long)row * HID;
        hr[lane]      = v0;
        hr[lane + 32] = v1;
        hr[lane + 64] = v2;
        s0 += v0; s1 += v1; s2 += v2;
        q0 += v0 * v0; q1 += v1 * v1; q2 += v2 * v2;
    }

    __shared__ float red[2 * HID];
    if (threadIdx.x < 2 * HID) red[threadIdx.x] = 0.0f;
    __syncthreads();
    atomicAdd(&red[lane],            s0);
    atomicAdd(&red[lane + 32],       s1);
    atomicAdd(&red[lane + 64],       s2);
    atomicAdd(&red[HID + lane],      q0);
    atomicAdd(&red[HID + lane + 32], q1);
    atomicAdd(&red[HID + lane + 64], q2);
    __syncthreads();
    if (threadIdx.x < HID) {
        atomicAdd(&stats[threadIdx.x],       red[threadIdx.x]);
        atomicAdd(&stats[HID + threadIdx.x], red[HID + threadIdx.x]);
    }
}

// ---------------- host launch ----------------
extern "C" void kernel_launch(void* const* d_in, const int* in_sizes, int n_in,
                              void* d_out, int out_size) {
    const float* x   = (const float*)d_in[0];
    const int*   ei  = (const int*)d_in[1];
    const float* W1  = (const float*)d_in[2];
    const float* b1  = (const float*)d_in[3];
    const float* g1  = (const float*)d_in[4];
    const float* be1 = (const float*)d_in[5];
    const float* W2  = (const float*)d_in[6];
    const float* b2  = (const float*)d_in[7];
    const float* g2  = (const float*)d_in[8];
    const float* be2 = (const float*)d_in[9];
    const float* Wp1 = (const float*)d_in[10];
    const float* bp1 = (const float*)d_in[11];
    const float* gp  = (const float*)d_in[12];
    const float* bep = (const float*)d_in[13];
    const float* Wp2 = (const float*)d_in[14];
    const float* bp2 = (const float*)d_in[15];
    float* out = (float*)d_out;

    float *xws, *hbuf, *dinv, *st1, *st2, *st3;
    cudaGetSymbolAddress((void**)&xws,  g_xws);
    cudaGetSymbolAddress((void**)&hbuf, g_h);
    cudaGetSymbolAddress((void**)&dinv, g_dinv);
    cudaGetSymbolAddress((void**)&st1,  g_stat1);
    cudaGetSymbolAddress((void**)&st2,  g_stat2);
    cudaGetSymbolAddress((void**)&st3,  g_stat3);

    const int gemm_grid = (NNODES + GBM - 1) / GBM;   // 391
    const int edge_grid = (NEDGES + 255) / 256;       // 3125
    const int agg_grid  = 1184;

    // dynamic smem sizes (words * 4 bytes)
    const int BBUF96 = AKW * (96 + 8);    // 1664
    const int BBUF64 = AKW * (64 + 8);    // 1152
    const int DS96 = (4 * ABUF + 4 * BBUF96) * 4;   // 67584 B
    const int DS64 = (4 * ABUF + 4 * BBUF64) * 4;   // 59392 B

    static cudaStream_t s_side = nullptr;
    static cudaEvent_t ev_fork = nullptr, ev_join = nullptr;
    if (s_side == nullptr) {
        cudaStreamCreateWithFlags(&s_side, cudaStreamNonBlocking);
        cudaEventCreateWithFlags(&ev_fork, cudaEventDisableTiming);
        cudaEventCreateWithFlags(&ev_join, cudaEventDisableTiming);
        cudaFuncSetAttribute(tgemm_k<HID, false, false>,
                             cudaFuncAttributeMaxDynamicSharedMemorySize, DS96);
        cudaFuncSetAttribute(tgemm_k<HID, false, true>,
                             cudaFuncAttributeMaxDynamicSharedMemorySize, DS96);
        cudaFuncSetAttribute(tgemm_k<PROJ, true, false>,
                             cudaFuncAttributeMaxDynamicSharedMemorySize, DS64);
    }

    // ---- fork: CSR build + dinv on side stream ----
    cudaEventRecord(ev_fork, 0);
    cudaStreamWaitEvent(s_side, ev_fork, 0);
    count_k<<<edge_grid, 256, 0, s_side>>>(ei);
    scan_k<<<1, 1024, 0, s_side>>>();
    fill_k<<<edge_grid, 256, 0, s_side>>>(ei);
    cudaEventRecord(ev_join, s_side);

    // ---- main stream: tgemm1 (raw x@W1, NO dinv dependency) ----
    tgemm_k<HID, false, false><<<gemm_grid, 256, DS96>>>(
        x, W1, nullptr, xws, NNODES, IN_DIM,
        nullptr, nullptr, nullptr, nullptr, nullptr);

    // ---- join ----
    cudaStreamWaitEvent(0, ev_join, 0);

    // ---- GCN layer 1 (dinv applied per-source inside agg) ----
    agg_k<true><<<agg_grid, 256>>>(b1, st1);

    // ---- GCN layer 2 (messages prescaled by dinv in tgemm2) ----
    tgemm_k<HID, false, false><<<gemm_grid, 256, DS96>>>(
        hbuf, W2, nullptr, xws, NNODES, HID,
        g1, be1, st1, dinv, nullptr);
    agg_k<false><<<agg_grid, 256>>>(b2, st2);

    // ---- projector linear 1 (stats fused) ----
    tgemm_k<HID, false, true><<<gemm_grid, 256, DS96>>>(
        hbuf, Wp1, bp1, xws, NNODES, HID,
        g2, be2, st2, nullptr, st3);

    // ---- projector linear 2 + fused L2 normalize ----
    tgemm_k<PROJ, true, false><<<gemm_grid, 256, DS64>>>(
        xws, Wp2, bp2, out, NNODES, HID,
        gp, bep, st3, nullptr, nullptr);
}

// round 15
// speedup vs baseline: 1.0089x; 1.0089x over previous
#include <cuda_runtime.h>
#include <cuda_bf16.h>
#include <math.h>

#define NNODES 50000
#define NEDGES 800000
#define IN_DIM 128
#define HID 96
#define PROJ 64
#define BN_EPS 1e-5f

// ---------------- scratch (device globals; statically zero-initialized) ----
__device__ __align__(16) float g_xws[NNODES * HID];   // GEMM outputs
__device__ __align__(16) float g_h[NNODES * HID];     // pre-BN activations
__device__ float g_dinv[NNODES];
__device__ float g_stat1[2 * HID];   // BN1 stats (sum | sumsq); scan_k zeroes
__device__ float g_stat2[2 * HID];   // BN2 stats
__device__ float g_stat3[2 * HID];   // projector BN stats
__device__ int   g_cnt[NNODES];      // zeroed statically; scan_k re-zeroes
__device__ int   g_rowptr[NNODES + 1];
__device__ int   g_cursor[NNODES];
__device__ int   g_csr[NEDGES];

// ---------------- CSR build (edge_index is int32: jnp x64 disabled) --------
__global__ void count_k(const int* __restrict__ ei) {
    int e = blockIdx.x * blockDim.x + threadIdx.x;
    if (e < NEDGES) atomicAdd(&g_cnt[ei[NEDGES + e]], 1);
}

// coalesced tiled exclusive scan; computes dinv; resets g_cnt; zeroes stats
__global__ void __launch_bounds__(1024) scan_k() {
    __shared__ int wsum[32];
    int t = threadIdx.x, lane = t & 31, w = t >> 5;
    if (t < 2 * HID) { g_stat1[t] = 0.f; g_stat2[t] = 0.f; g_stat3[t] = 0.f; }
    int carry = 0;
    for (int t0 = 0; t0 < NNODES; t0 += 1024) {
        int i = t0 + t;
        int v = (i < NNODES) ? g_cnt[i] : 0;
        if (i < NNODES) {
            g_dinv[i] = rsqrtf((float)(v + 1));
            g_cnt[i] = 0;
        }
        int x = v;
#pragma unroll
        for (int o = 1; o < 32; o <<= 1) {
            int y = __shfl_up_sync(0xffffffff, x, o);
            if (lane >= o) x += y;
        }
        if (lane == 31) wsum[w] = x;
        __syncthreads();
        if (w == 0) {
            int s = wsum[lane];
#pragma unroll
            for (int o = 1; o < 32; o <<= 1) {
                int y = __shfl_up_sync(0xffffffff, s, o);
                if (lane >= o) s += y;
            }
            wsum[lane] = s;
        }
        __syncthreads();
        int excl = x - v + (w > 0 ? wsum[w - 1] : 0) + carry;
        if (i < NNODES) { g_rowptr[i] = excl; g_cursor[i] = excl; }
        carry += wsum[31];
        __syncthreads();
    }
    if (t == 0) g_rowptr[NNODES] = carry;
}

__global__ void fill_k(const int* __restrict__ ei) {
    int e = blockIdx.x * blockDim.x + threadIdx.x;
    if (e < NEDGES) {
        int src = ei[e];
        int dst = ei[NEDGES + e];
        int pos = atomicAdd(&g_cursor[dst], 1);
        g_csr[pos] = src;
    }
}

// ------------- bf16-split tensor-core GEMM (3x m16n8k16) -------------------
#define GBM 128
#define GBK 32
#define AKW (GBK / 2)
#define AS_STRIDE 20

#define MMA_BF16(d, a0, a1, a2, a3, b0, b1)                                   \
    asm volatile(                                                             \
        "mma.sync.aligned.m16n8k16.row.col.f32.bf16.bf16.f32 "                \
        "{%0,%1,%2,%3},{%4,%5,%6,%7},{%8,%9},{%0,%1,%2,%3};"                  \
        : "+f"(d[0]), "+f"(d[1]), "+f"(d[2]), "+f"(d[3])                      \
        : "r"(a0), "r"(a1), "r"(a2), "r"(a3), "r"(b0), "r"(b1))

__device__ __forceinline__ void split2(float v0, float v1,
                                       unsigned& hw, unsigned& lw) {
    __nv_bfloat16 h0 = __float2bfloat16(v0);
    __nv_bfloat16 h1 = __float2bfloat16(v1);
    __nv_bfloat16 l0 = __float2bfloat16(v0 - __bfloat162float(h0));
    __nv_bfloat16 l1 = __float2bfloat16(v1 - __bfloat162float(h1));
    __nv_bfloat162 hh = __halves2bfloat162(h0, h1);
    __nv_bfloat162 ll = __halves2bfloat162(l0, l1);
    hw = *reinterpret_cast<unsigned*>(&hh);
    lw = *reinterpret_cast<unsigned*>(&ll);
}

template <int GBN, bool NORM, bool DO_STATS>
__global__ void __launch_bounds__(256, 2) tgemm_k(
    const float* __restrict__ A, const float* __restrict__ B,
    const float* __restrict__ bias, float* __restrict__ C,
    int M, int K,
    const float* __restrict__ gam, const float* __restrict__ bet,
    const float* __restrict__ stats,
    const float* __restrict__ rowscale, float* __restrict__ outstats)
{
    const int BS_STRIDE = GBN + 8;
    const int NJ = GBN / 16;

    __shared__ unsigned Ahi[GBM * AS_STRIDE];
    __shared__ unsigned Alo[GBM * AS_STRIDE];
    __shared__ unsigned Bhi[AKW * (GBN + 8)];
    __shared__ unsigned Blo[AKW * (GBN + 8)];
    __shared__ float tas[HID], tcs[HID];
    __shared__ float ssum[GBN], ssq[GBN];
    __shared__ float rowsq[GBM];

    int m0 = blockIdx.x * GBM;
    int tid = threadIdx.x;
    int wid = tid >> 5, lane = tid & 31;
    int g = lane >> 2, t4 = lane & 3;
    int wrow = wid >> 1;
    int wcol = wid & 1;
    int rbase = wrow * 32;
    int cbase = wcol * (GBN / 2);

    bool hasAff = (gam != nullptr);
    if (hasAff && tid < HID) {
        float mean = stats[tid] * (1.0f / NNODES);
        float var = stats[HID + tid] * (1.0f / NNODES) - mean * mean;
        float a = gam[tid] * rsqrtf(var + BN_EPS);
        tas[tid] = a;
        tcs[tid] = bet[tid] - a * mean;
    }
    if (DO_STATS && tid < GBN) { ssum[tid] = 0.0f; ssq[tid] = 0.0f; }
    if (NORM && tid < GBM) rowsq[tid] = 0.0f;
    __syncthreads();

    float acc[2][6][4];
#pragma unroll
    for (int i = 0; i < 2; i++)
#pragma unroll
        for (int j = 0; j < 6; j++)
#pragma unroll
            for (int q = 0; q < 4; q++) acc[i][j][q] = 0.0f;

    for (int k0 = 0; k0 < K; k0 += GBK) {
#pragma unroll
        for (int l = 0; l < 8; l++) {
            int idx = l * 256 + tid;
            int row = idx >> 4;
            int kw = idx & 15;
            int m = m0 + row;
            int kk = k0 + 2 * kw;
            float v0 = 0.0f, v1 = 0.0f;
            if (m < M) {
                float2 u = *(const float2*)(A + (long)m * K + kk);
                v0 = u.x; v1 = u.y;
                if (hasAff) {
                    v0 = fmaxf(fmaf(tas[kk], v0, tcs[kk]), 0.0f);
                    v1 = fmaxf(fmaf(tas[kk + 1], v1, tcs[kk + 1]), 0.0f);
                }
            }
            unsigned hw, lw;
            split2(v0, v1, hw, lw);
            Ahi[row * AS_STRIDE + kw] = hw;
            Alo[row * AS_STRIDE + kw] = lw;
        }
#pragma unroll
        for (int l = 0; l < NJ; l++) {
            int idx = l * 256 + tid;
            int kw = idx / GBN;
            int n = idx - kw * GBN;
            int kk = k0 + 2 * kw;
            float u0 = B[(long)kk * GBN + n];
            float u1 = B[(long)(kk + 1) * GBN + n];
            unsigned hw, lw;
            split2(u0, u1, hw, lw);
            Bhi[kw * BS_STRIDE + n] = hw;
            Blo[kw * BS_STRIDE + n] = lw;
        }
        __syncthreads();

#pragma unroll
        for (int kg = 0; kg < 2; kg++) {
            int kwb = kg * 8;
            unsigned ahi[2][4], alo[2][4];
#pragma unroll
            for (int i = 0; i < 2; i++) {
                int r0 = (rbase + i * 16 + g) * AS_STRIDE + kwb;
                int r1 = (rbase + i * 16 + 8 + g) * AS_STRIDE + kwb;
                ahi[i][0] = Ahi[r0 + t4];
                ahi[i][1] = Ahi[r1 + t4];
                ahi[i][2] = Ahi[r0 + 4 + t4];
                ahi[i][3] = Ahi[r1 + 4 + t4];
                alo[i][0] = Alo[r0 + t4];
                alo[i][1] = Alo[r1 + t4];
                alo[i][2] = Alo[r0 + 4 + t4];
                alo[i][3] = Alo[r1 + 4 + t4];
            }
            unsigned bhi[6][2], blo[6][2];
#pragma unroll
            for (int j = 0; j < NJ; j++) {
                int n = cbase + j * 8 + g;
                bhi[j][0] = Bhi[(kwb + t4) * BS_STRIDE + n];
                bhi[j][1] = Bhi[(kwb + 4 + t4) * BS_STRIDE + n];
                blo[j][0] = Blo[(kwb + t4) * BS_STRIDE + n];
                blo[j][1] = Blo[(kwb + 4 + t4) * BS_STRIDE + n];
            }
#pragma unroll
            for (int i = 0; i < 2; i++)
#pragma unroll
                for (int j = 0; j < NJ; j++) {
                    float* d = acc[i][j];
                    MMA_BF16(d, ahi[i][0], ahi[i][1], ahi[i][2], ahi[i][3],
                             blo[j][0], blo[j][1]);
                    MMA_BF16(d, alo[i][0], alo[i][1], alo[i][2], alo[i][3],
                             bhi[j][0], bhi[j][1]);
                    MMA_BF16(d, ahi[i][0], ahi[i][1], ahi[i][2], ahi[i][3],
                             bhi[j][0], bhi[j][1]);
                }
        }
        __syncthreads();
    }

    // ---- epilogue ----
    if (NORM) {
#pragma unroll
        for (int i = 0; i < 2; i++) {
#pragma unroll
            for (int h = 0; h < 2; h++) {
                int rloc = rbase + i * 16 + g + h * 8;
                int row = m0 + rloc;
                float lsq = 0.0f;
#pragma unroll
                for (int j = 0; j < NJ; j++) {
                    int col = cbase + j * 8 + t4 * 2;
                    float v0 = acc[i][j][h * 2 + 0] + bias[col];
                    float v1 = acc[i][j][h * 2 + 1] + bias[col + 1];
                    acc[i][j][h * 2 + 0] = v0;
                    acc[i][j][h * 2 + 1] = v1;
                    lsq += v0 * v0 + v1 * v1;
                }
                if (row < M) atomicAdd(&rowsq[rloc], lsq);
            }
        }
        __syncthreads();
#pragma unroll
        for (int i = 0; i < 2; i++) {
#pragma unroll
            for (int h = 0; h < 2; h++) {
                int rloc = rbase + i * 16 + g + h * 8;
                int row = m0 + rloc;
                if (row < M) {
                    float inv = 1.0f / fmaxf(sqrtf(rowsq[rloc]), 1e-12f);
#pragma unroll
                    for (int j = 0; j < NJ; j++) {
                        int col = cbase + j * 8 + t4 * 2;
                        float2 o;
                        o.x = acc[i][j][h * 2 + 0] * inv;
                        o.y = acc[i][j][h * 2 + 1] * inv;
                        *(float2*)(C + (long)row * GBN + col) = o;
                    }
                }
            }
        }
    } else {
#pragma unroll
        for (int j = 0; j < NJ; j++) {
            int col = cbase + j * 8 + t4 * 2;
            float ls0 = 0.f, ls1 = 0.f, lq0 = 0.f, lq1 = 0.f;
#pragma unroll
            for (int i = 0; i < 2; i++) {
#pragma unroll
                for (int h = 0; h < 2; h++) {
                    int row = m0 + rbase + i * 16 + g + h * 8;
                    if (row < M) {
                        float rs = rowscale ? rowscale[row] : 1.0f;
                        float v0 = acc[i][j][h * 2 + 0];
                        float v1 = acc[i][j][h * 2 + 1];
                        if (bias) { v0 += bias[col]; v1 += bias[col + 1]; }
                        v0 *= rs; v1 *= rs;
                        float2 o; o.x = v0; o.y = v1;
                        *(float2*)(C + (long)row * GBN + col) = o;
                        if (DO_STATS) {
                            ls0 += v0; ls1 += v1;
                            lq0 += v0 * v0; lq1 += v1 * v1;
                        }
                    }
                }
            }
            if (DO_STATS) {
                atomicAdd(&ssum[col], ls0);
                atomicAdd(&ssum[col + 1], ls1);
                atomicAdd(&ssq[col], lq0);
                atomicAdd(&ssq[col + 1], lq1);
            }
        }
        if (DO_STATS) {
            __syncthreads();
            if (tid < GBN) {
                atomicAdd(&outstats[tid], ssum[tid]);
                atomicAdd(&outstats[GBN + tid], ssq[tid]);
            }
        }
    }
}

// ------- fused aggregation + GCN epilogue + BN stats (warp per row) --------
template <bool SRCSCALE>
__global__ void __launch_bounds__(256) agg_k(const float* __restrict__ bias,
                                             float* __restrict__ stats) {
    int gwarp = (blockIdx.x * blockDim.x + threadIdx.x) >> 5;
    int nwarps = (gridDim.x * blockDim.x) >> 5;
    int lane = threadIdx.x & 31;

    const float b0 = bias[lane];
    const float b1 = bias[lane + 32];
    const float b2 = bias[lane + 64];

    float s0 = 0.f, s1 = 0.f, s2 = 0.f;
    float q0 = 0.f, q1 = 0.f, q2 = 0.f;

    for (int row = gwarp; row < NNODES; row += nwarps) {
        int st = g_rowptr[row];
        int en = g_rowptr[row + 1];
        float a0 = 0.f, a1 = 0.f, a2 = 0.f;

        for (int base = st; base < en; base += 32) {
            int idx = base + lane;
            int s = (idx < en) ? g_csr[idx] : 0;
            float dsc = SRCSCALE ? g_dinv[s] : 1.0f;
            int cnt = min(32, en - base);
#pragma unroll 8
            for (int j = 0; j < cnt; j++) {
                int sj = __shfl_sync(0xffffffff, s, j);
                const float* xr = g_xws + (long)sj * HID;
                if (SRCSCALE) {
                    float dj = __shfl_sync(0xffffffff, dsc, j);
                    a0 = fmaf(dj, xr[lane],      a0);
                    a1 = fmaf(dj, xr[lane + 32], a1);
                    a2 = fmaf(dj, xr[lane + 64], a2);
                } else {
                    a0 += xr[lane];
                    a1 += xr[lane + 32];
                    a2 += xr[lane + 64];
                }
            }
        }
        float di = g_dinv[row];
        const float* xs = g_xws + (long)row * HID;
        float selfscale = SRCSCALE ? di : 1.0f;
        float v0 = fmaf(di, fmaf(selfscale, xs[lane],      a0), b0);
        float v1 = fmaf(di, fmaf(selfscale, xs[lane + 32], a1), b1);
        float v2 = fmaf(di, fmaf(selfscale, xs[lane + 64], a2), b2);
        float* hr = g_h + (long)row * HID;
        hr[lane]      = v0;
        hr[lane + 32] = v1;
        hr[lane + 64] = v2;
        s0 += v0; s1 += v1; s2 += v2;
        q0 += v0 * v0; q1 += v1 * v1; q2 += v2 * v2;
    }

    __shared__ float red[2 * HID];
    if (threadIdx.x < 2 * HID) red[threadIdx.x] = 0.0f;
    __syncthreads();
    atomicAdd(&red[lane],            s0);
    atomicAdd(&red[lane + 32],       s1);
    atomicAdd(&red[lane + 64],       s2);
    atomicAdd(&red[HID + lane],      q0);
    atomicAdd(&red[HID + lane + 32], q1);
    atomicAdd(&red[HID + lane + 64], q2);
    __syncthreads();
    if (threadIdx.x < HID) {
        atomicAdd(&stats[threadIdx.x],       red[threadIdx.x]);
        atomicAdd(&stats[HID + threadIdx.x], red[HID + threadIdx.x]);
    }
}

// ---------------- host launch ----------------
extern "C" void kernel_launch(void* const* d_in, const int* in_sizes, int n_in,
                              void* d_out, int out_size) {
    const float* x   = (const float*)d_in[0];
    const int*   ei  = (const int*)d_in[1];
    const float* W1  = (const float*)d_in[2];
    const float* b1  = (const float*)d_in[3];
    const float* g1  = (const float*)d_in[4];
    const float* be1 = (const float*)d_in[5];
    const float* W2  = (const float*)d_in[6];
    const float* b2  = (const float*)d_in[7];
    const float* g2  = (const float*)d_in[8];
    const float* be2 = (const float*)d_in[9];
    const float* Wp1 = (const float*)d_in[10];
    const float* bp1 = (const float*)d_in[11];
    const float* gp  = (const float*)d_in[12];
    const float* bep = (const float*)d_in[13];
    const float* Wp2 = (const float*)d_in[14];
    const float* bp2 = (const float*)d_in[15];
    float* out = (float*)d_out;

    float *xws, *hbuf, *dinv, *st1, *st2, *st3;
    cudaGetSymbolAddress((void**)&xws,  g_xws);
    cudaGetSymbolAddress((void**)&hbuf, g_h);
    cudaGetSymbolAddress((void**)&dinv, g_dinv);
    cudaGetSymbolAddress((void**)&st1,  g_stat1);
    cudaGetSymbolAddress((void**)&st2,  g_stat2);
    cudaGetSymbolAddress((void**)&st3,  g_stat3);

    const int gemm_grid = (NNODES + GBM - 1) / GBM;   // 391
    const int edge_grid = (NEDGES + 255) / 256;       // 3125
    const int agg_grid  = 1184;

    static cudaStream_t s_side = nullptr;
    static cudaEvent_t ev_fork = nullptr, ev_join = nullptr;
    if (s_side == nullptr) {
        cudaStreamCreateWithFlags(&s_side, cudaStreamNonBlocking);
        cudaEventCreateWithFlags(&ev_fork, cudaEventDisableTiming);
        cudaEventCreateWithFlags(&ev_join, cudaEventDisableTiming);
    }

    // ---- fork: CSR build + dinv on side stream ----
    cudaEventRecord(ev_fork, 0);
    cudaStreamWaitEvent(s_side, ev_fork, 0);
    count_k<<<edge_grid, 256, 0, s_side>>>(ei);
    scan_k<<<1, 1024, 0, s_side>>>();
    fill_k<<<edge_grid, 256, 0, s_side>>>(ei);
    cudaEventRecord(ev_join, s_side);

    // ---- main stream: tgemm1 (raw x@W1, NO dinv dependency) ----
    tgemm_k<HID, false, false><<<gemm_grid, 256>>>(
        x, W1, nullptr, xws, NNODES, IN_DIM,
        nullptr, nullptr, nullptr, nullptr, nullptr);

    // ---- join ----
    cudaStreamWaitEvent(0, ev_join, 0);

    // ---- GCN layer 1 (dinv applied per-source inside agg) ----
    agg_k<true><<<agg_grid, 256>>>(b1, st1);

    // ---- GCN layer 2 (messages prescaled by dinv in tgemm2) ----
    tgemm_k<HID, false, false><<<gemm_grid, 256>>>(
        hbuf, W2, nullptr, xws, NNODES, HID,
        g1, be1, st1, dinv, nullptr);
    agg_k<false><<<agg_grid, 256>>>(b2, st2);

    // ---- projector linear 1 (stats fused) ----
    tgemm_k<HID, false, true><<<gemm_grid, 256>>>(
        hbuf, Wp1, bp1, xws, NNODES, HID,
        g2, be2, st2, nullptr, st3);

    // ---- projector linear 2 + fused L2 normalize ----
    tgemm_k<PROJ, true, false><<<gemm_grid, 256>>>(
        xws, Wp2, bp2, out, NNODES, HID,
        gp, bep, st3, nullptr, nullptr);
}

// round 16
// speedup vs baseline: 1.0757x; 1.0663x over previous
#include <cuda_runtime.h>
#include <cuda_bf16.h>
#include <math.h>

#define NNODES 50000
#define NEDGES 800000
#define IN_DIM 128
#define HID 96
#define PROJ 64
#define BN_EPS 1e-5f

// ---------------- scratch (device globals; statically zero-initialized) ----
__device__ __align__(16) float g_xws[NNODES * HID];   // GEMM outputs
__device__ __align__(16) float g_h[NNODES * HID];     // pre-BN activations
__device__ float g_dinv[NNODES];
__device__ float g_stat1[2 * HID];   // BN1 stats (sum | sumsq); scan_k zeroes
__device__ float g_stat2[2 * HID];   // BN2 stats
__device__ float g_stat3[2 * HID];   // projector BN stats
__device__ int   g_cnt[NNODES];      // zeroed statically; scan_k re-zeroes
__device__ int   g_rowptr[NNODES + 1];
__device__ int   g_cursor[NNODES];
__device__ int   g_csr[NEDGES];

// ---------------- CSR build (edge_index is int32: jnp x64 disabled) --------
__global__ void count_k(const int* __restrict__ ei) {
    int e = blockIdx.x * blockDim.x + threadIdx.x;
    if (e < NEDGES) atomicAdd(&g_cnt[ei[NEDGES + e]], 1);
}

// coalesced tiled exclusive scan; computes dinv; resets g_cnt; zeroes stats
__global__ void __launch_bounds__(1024) scan_k() {
    __shared__ int wsum[32];
    int t = threadIdx.x, lane = t & 31, w = t >> 5;
    if (t < 2 * HID) { g_stat1[t] = 0.f; g_stat2[t] = 0.f; g_stat3[t] = 0.f; }
    int carry = 0;
    for (int t0 = 0; t0 < NNODES; t0 += 1024) {
        int i = t0 + t;
        int v = (i < NNODES) ? g_cnt[i] : 0;
        if (i < NNODES) {
            g_dinv[i] = rsqrtf((float)(v + 1));
            g_cnt[i] = 0;
        }
        int x = v;
#pragma unroll
        for (int o = 1; o < 32; o <<= 1) {
            int y = __shfl_up_sync(0xffffffff, x, o);
            if (lane >= o) x += y;
        }
        if (lane == 31) wsum[w] = x;
        __syncthreads();
        if (w == 0) {
            int s = wsum[lane];
#pragma unroll
            for (int o = 1; o < 32; o <<= 1) {
                int y = __shfl_up_sync(0xffffffff, s, o);
                if (lane >= o) s += y;
            }
            wsum[lane] = s;
        }
        __syncthreads();
        int excl = x - v + (w > 0 ? wsum[w - 1] : 0) + carry;
        if (i < NNODES) { g_rowptr[i] = excl; g_cursor[i] = excl; }
        carry += wsum[31];
        __syncthreads();
    }
    if (t == 0) g_rowptr[NNODES] = carry;
}

__global__ void fill_k(const int* __restrict__ ei) {
    int e = blockIdx.x * blockDim.x + threadIdx.x;
    if (e < NEDGES) {
        int src = ei[e];
        int dst = ei[NEDGES + e];
        int pos = atomicAdd(&g_cursor[dst], 1);
        g_csr[pos] = src;
    }
}

// ------------- bf16-split tensor-core GEMM (3x m16n8k16) -------------------
// CTA tile 64 x GBN, 8 warps in 2(row) x 4(col) grid, warp tile 32 x GBN/4.
// 24 accum regs/thread @GBN=96 -> 3 CTAs/SM.
#define GBM 64
#define GBK 32
#define AKW (GBK / 2)
#define AS_STRIDE 20

#define MMA_BF16(d, a0, a1, a2, a3, b0, b1)                                   \
    asm volatile(                                                             \
        "mma.sync.aligned.m16n8k16.row.col.f32.bf16.bf16.f32 "                \
        "{%0,%1,%2,%3},{%4,%5,%6,%7},{%8,%9},{%0,%1,%2,%3};"                  \
        : "+f"(d[0]), "+f"(d[1]), "+f"(d[2]), "+f"(d[3])                      \
        : "r"(a0), "r"(a1), "r"(a2), "r"(a3), "r"(b0), "r"(b1))

__device__ __forceinline__ void split2(float v0, float v1,
                                       unsigned& hw, unsigned& lw) {
    __nv_bfloat16 h0 = __float2bfloat16(v0);
    __nv_bfloat16 h1 = __float2bfloat16(v1);
    __nv_bfloat16 l0 = __float2bfloat16(v0 - __bfloat162float(h0));
    __nv_bfloat16 l1 = __float2bfloat16(v1 - __bfloat162float(h1));
    __nv_bfloat162 hh = __halves2bfloat162(h0, h1);
    __nv_bfloat162 ll = __halves2bfloat162(l0, l1);
    hw = *reinterpret_cast<unsigned*>(&hh);
    lw = *reinterpret_cast<unsigned*>(&ll);
}

template <int GBN, bool NORM, bool DO_STATS>
__global__ void __launch_bounds__(256, 3) tgemm_k(
    const float* __restrict__ A, const float* __restrict__ B,
    const float* __restrict__ bias, float* __restrict__ C,
    int M, int K,
    const float* __restrict__ gam, const float* __restrict__ bet,
    const float* __restrict__ stats,
    const float* __restrict__ rowscale, float* __restrict__ outstats)
{
    const int BS_STRIDE = GBN + 8;
    const int NJS = GBN / 16;    // B staging loop count (6 or 4)
    const int NJW = GBN / 32;    // n8 tiles per warp (3 or 2)

    __shared__ unsigned Ahi[GBM * AS_STRIDE];      // 5.1KB
    __shared__ unsigned Alo[GBM * AS_STRIDE];      // 5.1KB
    __shared__ unsigned Bhi[AKW * (GBN + 8)];      // <=6.7KB
    __shared__ unsigned Blo[AKW * (GBN + 8)];      // <=6.7KB
    __shared__ float tas[HID], tcs[HID];
    __shared__ float ssum[GBN], ssq[GBN];
    __shared__ float rowsq[GBM];

    int m0 = blockIdx.x * GBM;
    int tid = threadIdx.x;
    int wid = tid >> 5, lane = tid & 31;
    int g = lane >> 2, t4 = lane & 3;
    int wrow = wid >> 2;            // 0..1
    int wcol = wid & 3;             // 0..3
    int rbase = wrow * 32;
    int cbase = wcol * (GBN / 4);   // 24 (GBN=96) or 16 (GBN=64)

    bool hasAff = (gam != nullptr);
    if (hasAff && tid < HID) {
        float mean = stats[tid] * (1.0f / NNODES);
        float var = stats[HID + tid] * (1.0f / NNODES) - mean * mean;
        float a = gam[tid] * rsqrtf(var + BN_EPS);
        tas[tid] = a;
        tcs[tid] = bet[tid] - a * mean;
    }
    if (DO_STATS && tid < GBN) { ssum[tid] = 0.0f; ssq[tid] = 0.0f; }
    if (NORM && tid < GBM) rowsq[tid] = 0.0f;
    __syncthreads();

    float acc[2][3][4];
#pragma unroll
    for (int i = 0; i < 2; i++)
#pragma unroll
        for (int j = 0; j < 3; j++)
#pragma unroll
            for (int q = 0; q < 4; q++) acc[i][j][q] = 0.0f;

    for (int k0 = 0; k0 < K; k0 += GBK) {
        // stage A tile 64x32 (16 packed words per row): 4 x 256
#pragma unroll
        for (int l = 0; l < 4; l++) {
            int idx = l * 256 + tid;
            int row = idx >> 4;
            int kw = idx & 15;
            int m = m0 + row;
            int kk = k0 + 2 * kw;
            float v0 = 0.0f, v1 = 0.0f;
            if (m < M) {
                float2 u = *(const float2*)(A + (long)m * K + kk);
                v0 = u.x; v1 = u.y;
                if (hasAff) {
                    v0 = fmaxf(fmaf(tas[kk], v0, tcs[kk]), 0.0f);
                    v1 = fmaxf(fmaf(tas[kk + 1], v1, tcs[kk + 1]), 0.0f);
                }
            }
            unsigned hw, lw;
            split2(v0, v1, hw, lw);
            Ahi[row * AS_STRIDE + kw] = hw;
            Alo[row * AS_STRIDE + kw] = lw;
        }
        // stage B tile 32 x GBN
#pragma unroll
        for (int l = 0; l < NJS; l++) {
            int idx = l * 256 + tid;
            int kw = idx / GBN;
            int n = idx - kw * GBN;
            int kk = k0 + 2 * kw;
            float u0 = B[(long)kk * GBN + n];
            float u1 = B[(long)(kk + 1) * GBN + n];
            unsigned hw, lw;
            split2(u0, u1, hw, lw);
            Bhi[kw * BS_STRIDE + n] = hw;
            Blo[kw * BS_STRIDE + n] = lw;
        }
        __syncthreads();

#pragma unroll
        for (int kg = 0; kg < 2; kg++) {
            int kwb = kg * 8;
            unsigned ahi[2][4], alo[2][4];
#pragma unroll
            for (int i = 0; i < 2; i++) {
                int r0 = (rbase + i * 16 + g) * AS_STRIDE + kwb;
                int r1 = (rbase + i * 16 + 8 + g) * AS_STRIDE + kwb;
                ahi[i][0] = Ahi[r0 + t4];
                ahi[i][1] = Ahi[r1 + t4];
                ahi[i][2] = Ahi[r0 + 4 + t4];
                ahi[i][3] = Ahi[r1 + 4 + t4];
                alo[i][0] = Alo[r0 + t4];
                alo[i][1] = Alo[r1 + t4];
                alo[i][2] = Alo[r0 + 4 + t4];
                alo[i][3] = Alo[r1 + 4 + t4];
            }
            unsigned bhi[3][2], blo[3][2];
#pragma unroll
            for (int j = 0; j < NJW; j++) {
                int n = cbase + j * 8 + g;
                bhi[j][0] = Bhi[(kwb + t4) * BS_STRIDE + n];
                bhi[j][1] = Bhi[(kwb + 4 + t4) * BS_STRIDE + n];
                blo[j][0] = Blo[(kwb + t4) * BS_STRIDE + n];
                blo[j][1] = Blo[(kwb + 4 + t4) * BS_STRIDE + n];
            }
#pragma unroll
            for (int i = 0; i < 2; i++)
#pragma unroll
                for (int j = 0; j < NJW; j++) {
                    float* d = acc[i][j];
                    MMA_BF16(d, ahi[i][0], ahi[i][1], ahi[i][2], ahi[i][3],
                             blo[j][0], blo[j][1]);
                    MMA_BF16(d, alo[i][0], alo[i][1], alo[i][2], alo[i][3],
                             bhi[j][0], bhi[j][1]);
                    MMA_BF16(d, ahi[i][0], ahi[i][1], ahi[i][2], ahi[i][3],
                             bhi[j][0], bhi[j][1]);
                }
        }
        __syncthreads();
    }

    // ---- epilogue ----
    if (NORM) {
#pragma unroll
        for (int i = 0; i < 2; i++) {
#pragma unroll
            for (int h = 0; h < 2; h++) {
                int rloc = rbase + i * 16 + g + h * 8;
                int row = m0 + rloc;
                float lsq = 0.0f;
#pragma unroll
                for (int j = 0; j < NJW; j++) {
                    int col = cbase + j * 8 + t4 * 2;
                    float v0 = acc[i][j][h * 2 + 0] + bias[col];
                    float v1 = acc[i][j][h * 2 + 1] + bias[col + 1];
                    acc[i][j][h * 2 + 0] = v0;
                    acc[i][j][h * 2 + 1] = v1;
                    lsq += v0 * v0 + v1 * v1;
                }
                if (row < M) atomicAdd(&rowsq[rloc], lsq);
            }
        }
        __syncthreads();
#pragma unroll
        for (int i = 0; i < 2; i++) {
#pragma unroll
            for (int h = 0; h < 2; h++) {
                int rloc = rbase + i * 16 + g + h * 8;
                int row = m0 + rloc;
                if (row < M) {
                    float inv = 1.0f / fmaxf(sqrtf(rowsq[rloc]), 1e-12f);
#pragma unroll
                    for (int j = 0; j < NJW; j++) {
                        int col = cbase + j * 8 + t4 * 2;
                        float2 o;
                        o.x = acc[i][j][h * 2 + 0] * inv;
                        o.y = acc[i][j][h * 2 + 1] * inv;
                        *(float2*)(C + (long)row * GBN + col) = o;
                    }
                }
            }
        }
    } else {
#pragma unroll
        for (int j = 0; j < NJW; j++) {
            int col = cbase + j * 8 + t4 * 2;
            float ls0 = 0.f, ls1 = 0.f, lq0 = 0.f, lq1 = 0.f;
#pragma unroll
            for (int i = 0; i < 2; i++) {
#pragma unroll
                for (int h = 0; h < 2; h++) {
                    int row = m0 + rbase + i * 16 + g + h * 8;
                    if (row < M) {
                        float rs = rowscale ? rowscale[row] : 1.0f;
                        float v0 = acc[i][j][h * 2 + 0];
                        float v1 = acc[i][j][h * 2 + 1];
                        if (bias) { v0 += bias[col]; v1 += bias[col + 1]; }
                        v0 *= rs; v1 *= rs;
                        float2 o; o.x = v0; o.y = v1;
                        *(float2*)(C + (long)row * GBN + col) = o;
                        if (DO_STATS) {
                            ls0 += v0; ls1 += v1;
                            lq0 += v0 * v0; lq1 += v1 * v1;
                        }
                    }
                }
            }
            if (DO_STATS) {
                atomicAdd(&ssum[col], ls0);
                atomicAdd(&ssum[col + 1], ls1);
                atomicAdd(&ssq[col], lq0);
                atomicAdd(&ssq[col + 1], lq1);
            }
        }
        if (DO_STATS) {
            __syncthreads();
            if (tid < GBN) {
                atomicAdd(&outstats[tid], ssum[tid]);
                atomicAdd(&outstats[GBN + tid], ssq[tid]);
            }
        }
    }
}

// ------- fused aggregation + GCN epilogue + BN stats (warp per row) --------
template <bool SRCSCALE>
__global__ void __launch_bounds__(256) agg_k(const float* __restrict__ bias,
                                             float* __restrict__ stats) {
    int gwarp = (blockIdx.x * blockDim.x + threadIdx.x) >> 5;
    int nwarps = (gridDim.x * blockDim.x) >> 5;
    int lane = threadIdx.x & 31;

    const float b0 = bias[lane];
    const float b1 = bias[lane + 32];
    const float b2 = bias[lane + 64];

    float s0 = 0.f, s1 = 0.f, s2 = 0.f;
    float q0 = 0.f, q1 = 0.f, q2 = 0.f;

    for (int row = gwarp; row < NNODES; row += nwarps) {
        int st = g_rowptr[row];
        int en = g_rowptr[row + 1];
        float a0 = 0.f, a1 = 0.f, a2 = 0.f;

        for (int base = st; base < en; base += 32) {
            int idx = base + lane;
            int s = (idx < en) ? g_csr[idx] : 0;
            float dsc = SRCSCALE ? g_dinv[s] : 1.0f;
            int cnt = min(32, en - base);
#pragma unroll 4
            for (int j = 0; j < cnt; j++) {
                int sj = __shfl_sync(0xffffffff, s, j);
                const float* xr = g_xws + (long)sj * HID;
                if (SRCSCALE) {
                    float dj = __shfl_sync(0xffffffff, dsc, j);
                    a0 = fmaf(dj, xr[lane],      a0);
                    a1 = fmaf(dj, xr[lane + 32], a1);
                    a2 = fmaf(dj, xr[lane + 64], a2);
                } else {
                    a0 += xr[lane];
                    a1 += xr[lane + 32];
                    a2 += xr[lane + 64];
                }
            }
        }
        float di = g_dinv[row];
        const float* xs = g_xws + (long)row * HID;
        float selfscale = SRCSCALE ? di : 1.0f;
        float v0 = fmaf(di, fmaf(selfscale, xs[lane],      a0), b0);
        float v1 = fmaf(di, fmaf(selfscale, xs[lane + 32], a1), b1);
        float v2 = fmaf(di, fmaf(selfscale, xs[lane + 64], a2), b2);
        float* hr = g_h + (long)row * HID;
        hr[lane]      = v0;
        hr[lane + 32] = v1;
        hr[lane + 64] = v2;
        s0 += v0; s1 += v1; s2 += v2;
        q0 += v0 * v0; q1 += v1 * v1; q2 += v2 * v2;
    }

    __shared__ float red[2 * HID];
    if (threadIdx.x < 2 * HID) red[threadIdx.x] = 0.0f;
    __syncthreads();
    atomicAdd(&red[lane],            s0);
    atomicAdd(&red[lane + 32],       s1);
    atomicAdd(&red[lane + 64],       s2);
    atomicAdd(&red[HID + lane],      q0);
    atomicAdd(&red[HID + lane + 32], q1);
    atomicAdd(&red[HID + lane + 64], q2);
    __syncthreads();
    if (threadIdx.x < HID) {
        atomicAdd(&stats[threadIdx.x],       red[threadIdx.x]);
        atomicAdd(&stats[HID + threadIdx.x], red[HID + threadIdx.x]);
    }
}

// ---------------- host launch ----------------
extern "C" void kernel_launch(void* const* d_in, const int* in_sizes, int n_in,
                              void* d_out, int out_size) {
    const float* x   = (const float*)d_in[0];
    const int*   ei  = (const int*)d_in[1];
    const float* W1  = (const float*)d_in[2];
    const float* b1  = (const float*)d_in[3];
    const float* g1  = (const float*)d_in[4];
    const float* be1 = (const float*)d_in[5];
    const float* W2  = (const float*)d_in[6];
    const float* b2  = (const float*)d_in[7];
    const float* g2  = (const float*)d_in[8];
    const float* be2 = (const float*)d_in[9];
    const float* Wp1 = (const float*)d_in[10];
    const float* bp1 = (const float*)d_in[11];
    const float* gp  = (const float*)d_in[12];
    const float* bep = (const float*)d_in[13];
    const float* Wp2 = (const float*)d_in[14];
    const float* bp2 = (const float*)d_in[15];
    float* out = (float*)d_out;

    float *xws, *hbuf, *dinv, *st1, *st2, *st3;
    cudaGetSymbolAddress((void**)&xws,  g_xws);
    cudaGetSymbolAddress((void**)&hbuf, g_h);
    cudaGetSymbolAddress((void**)&dinv, g_dinv);
    cudaGetSymbolAddress((void**)&st1,  g_stat1);
    cudaGetSymbolAddress((void**)&st2,  g_stat2);
    cudaGetSymbolAddress((void**)&st3,  g_stat3);

    const int gemm_grid = (NNODES + GBM - 1) / GBM;   // 782
    const int edge_grid = (NEDGES + 255) / 256;       // 3125
    const int agg_grid  = 1184;

    static cudaStream_t s_side = nullptr;
    static cudaEvent_t ev_fork = nullptr, ev_join = nullptr;
    if (s_side == nullptr) {
        cudaStreamCreateWithFlags(&s_side, cudaStreamNonBlocking);
        cudaEventCreateWithFlags(&ev_fork, cudaEventDisableTiming);
        cudaEventCreateWithFlags(&ev_join, cudaEventDisableTiming);
    }

    // ---- fork: CSR build + dinv on side stream ----
    cudaEventRecord(ev_fork, 0);
    cudaStreamWaitEvent(s_side, ev_fork, 0);
    count_k<<<edge_grid, 256, 0, s_side>>>(ei);
    scan_k<<<1, 1024, 0, s_side>>>();
    fill_k<<<edge_grid, 256, 0, s_side>>>(ei);
    cudaEventRecord(ev_join, s_side);

    // ---- main stream: tgemm1 (raw x@W1, NO dinv dependency) ----
    tgemm_k<HID, false, false><<<gemm_grid, 256>>>(
        x, W1, nullptr, xws, NNODES, IN_DIM,
        nullptr, nullptr, nullptr, nullptr, nullptr);

    // ---- join ----
    cudaStreamWaitEvent(0, ev_join, 0);

    // ---- GCN layer 1 (dinv applied per-source inside agg) ----
    agg_k<true><<<agg_grid, 256>>>(b1, st1);

    // ---- GCN layer 2 (messages prescaled by dinv in tgemm2) ----
    tgemm_k<HID, false, false><<<gemm_grid, 256>>>(
        hbuf, W2, nullptr, xws, NNODES, HID,
        g1, be1, st1, dinv, nullptr);
    agg_k<false><<<agg_grid, 256>>>(b2, st2);

    // ---- projector linear 1 (stats fused) ----
    tgemm_k<HID, false, true><<<gemm_grid, 256>>>(
        hbuf, Wp1, bp1, xws, NNODES, HID,
        g2, be2, st2, nullptr, st3);

    // ---- projector linear 2 + fused L2 normalize ----
    tgemm_k<PROJ, true, false><<<gemm_grid, 256>>>(
        xws, Wp2, bp2, out, NNODES, HID,
        gp, bep, st3, nullptr, nullptr);
}

// round 17
// speedup vs baseline: 1.1549x; 1.0736x over previous
#include <cuda_runtime.h>
#include <cuda_bf16.h>
#include <math.h>

#define NNODES 50000
#define NEDGES 800000
#define IN_DIM 128
#define HID 96
#define PROJ 64
#define BN_EPS 1e-5f

// ---------------- scratch (device globals; statically zero-initialized) ----
__device__ __align__(16) float g_xws[NNODES * HID];   // GEMM outputs
__device__ __align__(16) float g_h[NNODES * HID];     // pre-BN activations
__device__ float g_dinv[NNODES];
__device__ float g_stat1[2 * HID];   // BN1 stats (sum | sumsq); scan_k zeroes
__device__ float g_stat2[2 * HID];   // BN2 stats
__device__ float g_stat3[2 * HID];   // projector BN stats
__device__ int   g_cnt[NNODES];      // zeroed statically; scan_k re-zeroes
__device__ int   g_rowptr[NNODES + 1];
__device__ int   g_cursor[NNODES];
__device__ int   g_csr[NEDGES];
// pre-split weights: packed bf16x2 words, layout [kw][n], kw = k/2
__device__ unsigned g_bh1[(IN_DIM / 2) * HID], g_bl1[(IN_DIM / 2) * HID];
__device__ unsigned g_bh2[(HID / 2) * HID],    g_bl2[(HID / 2) * HID];
__device__ unsigned g_bh3[(HID / 2) * HID],    g_bl3[(HID / 2) * HID];
__device__ unsigned g_bh4[(HID / 2) * PROJ],   g_bl4[(HID / 2) * PROJ];

__device__ __forceinline__ void split2(float v0, float v1,
                                       unsigned& hw, unsigned& lw) {
    __nv_bfloat16 h0 = __float2bfloat16(v0);
    __nv_bfloat16 h1 = __float2bfloat16(v1);
    __nv_bfloat16 l0 = __float2bfloat16(v0 - __bfloat162float(h0));
    __nv_bfloat16 l1 = __float2bfloat16(v1 - __bfloat162float(h1));
    __nv_bfloat162 hh = __halves2bfloat162(h0, h1);
    __nv_bfloat162 ll = __halves2bfloat162(l0, l1);
    hw = *reinterpret_cast<unsigned*>(&hh);
    lw = *reinterpret_cast<unsigned*>(&ll);
}

// ---------------- weight pre-split (once per launch, ~18k words) ----------
__device__ void split_one(const float* __restrict__ W, unsigned* __restrict__ H,
                          unsigned* __restrict__ L, int K, int N,
                          int gid, int stride) {
    int total = (K / 2) * N;
    for (int i = gid; i < total; i += stride) {
        int kw = i / N;
        int n = i - kw * N;
        split2(W[(long)(2 * kw) * N + n], W[(long)(2 * kw + 1) * N + n],
               H[i], L[i]);
    }
}

__global__ void splitw_k(const float* __restrict__ W1,
                         const float* __restrict__ W2,
                         const float* __restrict__ Wp1,
                         const float* __restrict__ Wp2) {
    int gid = blockIdx.x * blockDim.x + threadIdx.x;
    int stride = gridDim.x * blockDim.x;
    split_one(W1,  g_bh1, g_bl1, IN_DIM, HID, gid, stride);
    split_one(W2,  g_bh2, g_bl2, HID,    HID, gid, stride);
    split_one(Wp1, g_bh3, g_bl3, HID,    HID, gid, stride);
    split_one(Wp2, g_bh4, g_bl4, HID,    PROJ, gid, stride);
}

// ---------------- CSR build (edge_index is int32: jnp x64 disabled) --------
__global__ void count_k(const int* __restrict__ ei) {
    int e = blockIdx.x * blockDim.x + threadIdx.x;
    if (e < NEDGES) atomicAdd(&g_cnt[ei[NEDGES + e]], 1);
}

// coalesced tiled exclusive scan; computes dinv; resets g_cnt; zeroes stats
__global__ void __launch_bounds__(1024) scan_k() {
    __shared__ int wsum[32];
    int t = threadIdx.x, lane = t & 31, w = t >> 5;
    if (t < 2 * HID) { g_stat1[t] = 0.f; g_stat2[t] = 0.f; g_stat3[t] = 0.f; }
    int carry = 0;
    for (int t0 = 0; t0 < NNODES; t0 += 1024) {
        int i = t0 + t;
        int v = (i < NNODES) ? g_cnt[i] : 0;
        if (i < NNODES) {
            g_dinv[i] = rsqrtf((float)(v + 1));
            g_cnt[i] = 0;
        }
        int x = v;
#pragma unroll
        for (int o = 1; o < 32; o <<= 1) {
            int y = __shfl_up_sync(0xffffffff, x, o);
            if (lane >= o) x += y;
        }
        if (lane == 31) wsum[w] = x;
        __syncthreads();
        if (w == 0) {
            int s = wsum[lane];
#pragma unroll
            for (int o = 1; o < 32; o <<= 1) {
                int y = __shfl_up_sync(0xffffffff, s, o);
                if (lane >= o) s += y;
            }
            wsum[lane] = s;
        }
        __syncthreads();
        int excl = x - v + (w > 0 ? wsum[w - 1] : 0) + carry;
        if (i < NNODES) { g_rowptr[i] = excl; g_cursor[i] = excl; }
        carry += wsum[31];
        __syncthreads();
    }
    if (t == 0) g_rowptr[NNODES] = carry;
}

__global__ void fill_k(const int* __restrict__ ei) {
    int e = blockIdx.x * blockDim.x + threadIdx.x;
    if (e < NEDGES) {
        int src = ei[e];
        int dst = ei[NEDGES + e];
        int pos = atomicAdd(&g_cursor[dst], 1);
        g_csr[pos] = src;
    }
}

// ------------- bf16-split tensor-core GEMM (3x m16n8k16) -------------------
// CTA tile 64 x GBN, 8 warps 2x4, warp tile 32 x GBN/4, 3 CTAs/SM.
// B arrives pre-split (packed bf16x2 hi/lo words, [kw][n] layout).
#define GBM 64
#define GBK 32
#define AKW (GBK / 2)
#define AS_STRIDE 20

#define MMA_BF16(d, a0, a1, a2, a3, b0, b1)                                   \
    asm volatile(                                                             \
        "mma.sync.aligned.m16n8k16.row.col.f32.bf16.bf16.f32 "                \
        "{%0,%1,%2,%3},{%4,%5,%6,%7},{%8,%9},{%0,%1,%2,%3};"                  \
        : "+f"(d[0]), "+f"(d[1]), "+f"(d[2]), "+f"(d[3])                      \
        : "r"(a0), "r"(a1), "r"(a2), "r"(a3), "r"(b0), "r"(b1))

template <int GBN, bool NORM, bool DO_STATS>
__global__ void __launch_bounds__(256, 3) tgemm_k(
    const float* __restrict__ A,
    const unsigned* __restrict__ GBh, const unsigned* __restrict__ GBl,
    const float* __restrict__ bias, float* __restrict__ C,
    int M, int K,
    const float* __restrict__ gam, const float* __restrict__ bet,
    const float* __restrict__ stats,
    const float* __restrict__ rowscale, float* __restrict__ outstats)
{
    const int BS_STRIDE = GBN + 8;
    const int NJS = GBN / 16;    // B staging loop count (6 or 4)
    const int NJW = GBN / 32;    // n8 tiles per warp (3 or 2)

    __shared__ unsigned Ahi[GBM * AS_STRIDE];
    __shared__ unsigned Alo[GBM * AS_STRIDE];
    __shared__ unsigned Bhi[AKW * (GBN + 8)];
    __shared__ unsigned Blo[AKW * (GBN + 8)];
    __shared__ float tas[HID], tcs[HID];
    __shared__ float ssum[GBN], ssq[GBN];
    __shared__ float rowsq[GBM];

    int m0 = blockIdx.x * GBM;
    int tid = threadIdx.x;
    int wid = tid >> 5, lane = tid & 31;
    int g = lane >> 2, t4 = lane & 3;
    int wrow = wid >> 2;            // 0..1
    int wcol = wid & 3;             // 0..3
    int rbase = wrow * 32;
    int cbase = wcol * (GBN / 4);

    bool hasAff = (gam != nullptr);
    if (hasAff && tid < HID) {
        float mean = stats[tid] * (1.0f / NNODES);
        float var = stats[HID + tid] * (1.0f / NNODES) - mean * mean;
        float a = gam[tid] * rsqrtf(var + BN_EPS);
        tas[tid] = a;
        tcs[tid] = bet[tid] - a * mean;
    }
    if (DO_STATS && tid < GBN) { ssum[tid] = 0.0f; ssq[tid] = 0.0f; }
    if (NORM && tid < GBM) rowsq[tid] = 0.0f;
    __syncthreads();

    float acc[2][3][4];
#pragma unroll
    for (int i = 0; i < 2; i++)
#pragma unroll
        for (int j = 0; j < 3; j++)
#pragma unroll
            for (int q = 0; q < 4; q++) acc[i][j][q] = 0.0f;

    for (int k0 = 0; k0 < K; k0 += GBK) {
        // stage A tile 64x32 (split in-kernel; A is data-dependent)
#pragma unroll
        for (int l = 0; l < 4; l++) {
            int idx = l * 256 + tid;
            int row = idx >> 4;
            int kw = idx & 15;
            int m = m0 + row;
            int kk = k0 + 2 * kw;
            float v0 = 0.0f, v1 = 0.0f;
            if (m < M) {
                float2 u = *(const float2*)(A + (long)m * K + kk);
                v0 = u.x; v1 = u.y;
                if (hasAff) {
                    v0 = fmaxf(fmaf(tas[kk], v0, tcs[kk]), 0.0f);
                    v1 = fmaxf(fmaf(tas[kk + 1], v1, tcs[kk + 1]), 0.0f);
                }
            }
            unsigned hw, lw;
            split2(v0, v1, hw, lw);
            Ahi[row * AS_STRIDE + kw] = hw;
            Alo[row * AS_STRIDE + kw] = lw;
        }
        // stage B tile 32 x GBN: straight copy of pre-split words
#pragma unroll
        for (int l = 0; l < NJS; l++) {
            int idx = l * 256 + tid;
            int kw = idx / GBN;
            int n = idx - kw * GBN;
            int widx = (k0 / 2 + kw) * GBN + n;
            Bhi[kw * BS_STRIDE + n] = GBh[widx];
            Blo[kw * BS_STRIDE + n] = GBl[widx];
        }
        __syncthreads();

#pragma unroll
        for (int kg = 0; kg < 2; kg++) {
            int kwb = kg * 8;
            unsigned ahi[2][4], alo[2][4];
#pragma unroll
            for (int i = 0; i < 2; i++) {
                int r0 = (rbase + i * 16 + g) * AS_STRIDE + kwb;
                int r1 = (rbase + i * 16 + 8 + g) * AS_STRIDE + kwb;
                ahi[i][0] = Ahi[r0 + t4];
                ahi[i][1] = Ahi[r1 + t4];
                ahi[i][2] = Ahi[r0 + 4 + t4];
                ahi[i][3] = Ahi[r1 + 4 + t4];
                alo[i][0] = Alo[r0 + t4];
                alo[i][1] = Alo[r1 + t4];
                alo[i][2] = Alo[r0 + 4 + t4];
                alo[i][3] = Alo[r1 + 4 + t4];
            }
            unsigned bhi[3][2], blo[3][2];
#pragma unroll
            for (int j = 0; j < NJW; j++) {
                int n = cbase + j * 8 + g;
                bhi[j][0] = Bhi[(kwb + t4) * BS_STRIDE + n];
                bhi[j][1] = Bhi[(kwb + 4 + t4) * BS_STRIDE + n];
                blo[j][0] = Blo[(kwb + t4) * BS_STRIDE + n];
                blo[j][1] = Blo[(kwb + 4 + t4) * BS_STRIDE + n];
            }
#pragma unroll
            for (int i = 0; i < 2; i++)
#pragma unroll
                for (int j = 0; j < NJW; j++) {
                    float* d = acc[i][j];
                    MMA_BF16(d, ahi[i][0], ahi[i][1], ahi[i][2], ahi[i][3],
                             blo[j][0], blo[j][1]);
                    MMA_BF16(d, alo[i][0], alo[i][1], alo[i][2], alo[i][3],
                             bhi[j][0], bhi[j][1]);
                    MMA_BF16(d, ahi[i][0], ahi[i][1], ahi[i][2], ahi[i][3],
                             bhi[j][0], bhi[j][1]);
                }
        }
        __syncthreads();
    }

    // ---- epilogue ----
    if (NORM) {
#pragma unroll
        for (int i = 0; i < 2; i++) {
#pragma unroll
            for (int h = 0; h < 2; h++) {
                int rloc = rbase + i * 16 + g + h * 8;
                int row = m0 + rloc;
                float lsq = 0.0f;
#pragma unroll
                for (int j = 0; j < NJW; j++) {
                    int col = cbase + j * 8 + t4 * 2;
                    float v0 = acc[i][j][h * 2 + 0] + bias[col];
                    float v1 = acc[i][j][h * 2 + 1] + bias[col + 1];
                    acc[i][j][h * 2 + 0] = v0;
                    acc[i][j][h * 2 + 1] = v1;
                    lsq += v0 * v0 + v1 * v1;
                }
                if (row < M) atomicAdd(&rowsq[rloc], lsq);
            }
        }
        __syncthreads();
#pragma unroll
        for (int i = 0; i < 2; i++) {
#pragma unroll
            for (int h = 0; h < 2; h++) {
                int rloc = rbase + i * 16 + g + h * 8;
                int row = m0 + rloc;
                if (row < M) {
                    float inv = 1.0f / fmaxf(sqrtf(rowsq[rloc]), 1e-12f);
#pragma unroll
                    for (int j = 0; j < NJW; j++) {
                        int col = cbase + j * 8 + t4 * 2;
                        float2 o;
                        o.x = acc[i][j][h * 2 + 0] * inv;
                        o.y = acc[i][j][h * 2 + 1] * inv;
                        *(float2*)(C + (long)row * GBN + col) = o;
                    }
                }
            }
        }
    } else {
#pragma unroll
        for (int j = 0; j < NJW; j++) {
            int col = cbase + j * 8 + t4 * 2;
            float ls0 = 0.f, ls1 = 0.f, lq0 = 0.f, lq1 = 0.f;
#pragma unroll
            for (int i = 0; i < 2; i++) {
#pragma unroll
                for (int h = 0; h < 2; h++) {
                    int row = m0 + rbase + i * 16 + g + h * 8;
                    if (row < M) {
                        float rs = rowscale ? rowscale[row] : 1.0f;
                        float v0 = acc[i][j][h * 2 + 0];
                        float v1 = acc[i][j][h * 2 + 1];
                        if (bias) { v0 += bias[col]; v1 += bias[col + 1]; }
                        v0 *= rs; v1 *= rs;
                        float2 o; o.x = v0; o.y = v1;
                        *(float2*)(C + (long)row * GBN + col) = o;
                        if (DO_STATS) {
                            ls0 += v0; ls1 += v1;
                            lq0 += v0 * v0; lq1 += v1 * v1;
                        }
                    }
                }
            }
            if (DO_STATS) {
                atomicAdd(&ssum[col], ls0);
                atomicAdd(&ssum[col + 1], ls1);
                atomicAdd(&ssq[col], lq0);
                atomicAdd(&ssq[col + 1], lq1);
            }
        }
        if (DO_STATS) {
            __syncthreads();
            if (tid < GBN) {
                atomicAdd(&outstats[tid], ssum[tid]);
                atomicAdd(&outstats[GBN + tid], ssq[tid]);
            }
        }
    }
}

// ------- fused aggregation + GCN epilogue + BN stats (warp per row) --------
template <bool SRCSCALE>
__global__ void __launch_bounds__(256) agg_k(const float* __restrict__ bias,
                                             float* __restrict__ stats) {
    int gwarp = (blockIdx.x * blockDim.x + threadIdx.x) >> 5;
    int nwarps = (gridDim.x * blockDim.x) >> 5;
    int lane = threadIdx.x & 31;

    const float b0 = bias[lane];
    const float b1 = bias[lane + 32];
    const float b2 = bias[lane + 64];

    float s0 = 0.f, s1 = 0.f, s2 = 0.f;
    float q0 = 0.f, q1 = 0.f, q2 = 0.f;

    for (int row = gwarp; row < NNODES; row += nwarps) {
        int st = g_rowptr[row];
        int en = g_rowptr[row + 1];
        float a0 = 0.f, a1 = 0.f, a2 = 0.f;

        for (int base = st; base < en; base += 32) {
            int idx = base + lane;
            int s = (idx < en) ? g_csr[idx] : 0;
            float dsc = SRCSCALE ? g_dinv[s] : 1.0f;
            int cnt = min(32, en - base);
#pragma unroll 4
            for (int j = 0; j < cnt; j++) {
                int sj = __shfl_sync(0xffffffff, s, j);
                const float* xr = g_xws + (long)sj * HID;
                if (SRCSCALE) {
                    float dj = __shfl_sync(0xffffffff, dsc, j);
                    a0 = fmaf(dj, xr[lane],      a0);
                    a1 = fmaf(dj, xr[lane + 32], a1);
                    a2 = fmaf(dj, xr[lane + 64], a2);
                } else {
                    a0 += xr[lane];
                    a1 += xr[lane + 32];
                    a2 += xr[lane + 64];
                }
            }
        }
        float di = g_dinv[row];
        const float* xs = g_xws + (long)row * HID;
        float selfscale = SRCSCALE ? di : 1.0f;
        float v0 = fmaf(di, fmaf(selfscale, xs[lane],      a0), b0);
        float v1 = fmaf(di, fmaf(selfscale, xs[lane + 32], a1), b1);
        float v2 = fmaf(di, fmaf(selfscale, xs[lane + 64], a2), b2);
        float* hr = g_h + (long)row * HID;
        hr[lane]      = v0;
        hr[lane + 32] = v1;
        hr[lane + 64] = v2;
        s0 += v0; s1 += v1; s2 += v2;
        q0 += v0 * v0; q1 += v1 * v1; q2 += v2 * v2;
    }

    __shared__ float red[2 * HID];
    if (threadIdx.x < 2 * HID) red[threadIdx.x] = 0.0f;
    __syncthreads();
    atomicAdd(&red[lane],            s0);
    atomicAdd(&red[lane + 32],       s1);
    atomicAdd(&red[lane + 64],       s2);
    atomicAdd(&red[HID + lane],      q0);
    atomicAdd(&red[HID + lane + 32], q1);
    atomicAdd(&red[HID + lane + 64], q2);
    __syncthreads();
    if (threadIdx.x < HID) {
        atomicAdd(&stats[threadIdx.x],       red[threadIdx.x]);
        atomicAdd(&stats[HID + threadIdx.x], red[HID + threadIdx.x]);
    }
}

// ---------------- host launch ----------------
extern "C" void kernel_launch(void* const* d_in, const int* in_sizes, int n_in,
                              void* d_out, int out_size) {
    const float* x   = (const float*)d_in[0];
    const int*   ei  = (const int*)d_in[1];
    const float* W1  = (const float*)d_in[2];
    const float* b1  = (const float*)d_in[3];
    const float* g1  = (const float*)d_in[4];
    const float* be1 = (const float*)d_in[5];
    const float* W2  = (const float*)d_in[6];
    const float* b2  = (const float*)d_in[7];
    const float* g2  = (const float*)d_in[8];
    const float* be2 = (const float*)d_in[9];
    const float* Wp1 = (const float*)d_in[10];
    const float* bp1 = (const float*)d_in[11];
    const float* gp  = (const float*)d_in[12];
    const float* bep = (const float*)d_in[13];
    const float* Wp2 = (const float*)d_in[14];
    const float* bp2 = (const float*)d_in[15];
    float* out = (float*)d_out;

    float *xws, *hbuf, *dinv, *st1, *st2, *st3;
    unsigned *bh1, *bl1, *bh2, *bl2, *bh3, *bl3, *bh4, *bl4;
    cudaGetSymbolAddress((void**)&xws,  g_xws);
    cudaGetSymbolAddress((void**)&hbuf, g_h);
    cudaGetSymbolAddress((void**)&dinv, g_dinv);
    cudaGetSymbolAddress((void**)&st1,  g_stat1);
    cudaGetSymbolAddress((void**)&st2,  g_stat2);
    cudaGetSymbolAddress((void**)&st3,  g_stat3);
    cudaGetSymbolAddress((void**)&bh1,  g_bh1);
    cudaGetSymbolAddress((void**)&bl1,  g_bl1);
    cudaGetSymbolAddress((void**)&bh2,  g_bh2);
    cudaGetSymbolAddress((void**)&bl2,  g_bl2);
    cudaGetSymbolAddress((void**)&bh3,  g_bh3);
    cudaGetSymbolAddress((void**)&bl3,  g_bl3);
    cudaGetSymbolAddress((void**)&bh4,  g_bh4);
    cudaGetSymbolAddress((void**)&bl4,  g_bl4);

    const int gemm_grid = (NNODES + GBM - 1) / GBM;   // 782
    const int edge_grid = (NEDGES + 255) / 256;       // 3125
    const int agg_grid  = 1184;

    static cudaStream_t s_side = nullptr;
    static cudaEvent_t ev_fork = nullptr, ev_join = nullptr;
    if (s_side == nullptr) {
        cudaStreamCreateWithFlags(&s_side, cudaStreamNonBlocking);
        cudaEventCreateWithFlags(&ev_fork, cudaEventDisableTiming);
        cudaEventCreateWithFlags(&ev_join, cudaEventDisableTiming);
    }

    // ---- fork: CSR build + dinv on side stream ----
    cudaEventRecord(ev_fork, 0);
    cudaStreamWaitEvent(s_side, ev_fork, 0);
    count_k<<<edge_grid, 256, 0, s_side>>>(ei);
    scan_k<<<1, 1024, 0, s_side>>>();
    fill_k<<<edge_grid, 256, 0, s_side>>>(ei);
    cudaEventRecord(ev_join, s_side);

    // ---- main stream: weight pre-split, then tgemm1 (no dinv dependency) --
    splitw_k<<<24, 256>>>(W1, W2, Wp1, Wp2);
    tgemm_k<HID, false, false><<<gemm_grid, 256>>>(
        x, bh1, bl1, nullptr, xws, NNODES, IN_DIM,
        nullptr, nullptr, nullptr, nullptr, nullptr);

    // ---- join ----
    cudaStreamWaitEvent(0, ev_join, 0);

    // ---- GCN layer 1 (dinv applied per-source inside agg) ----
    agg_k<true><<<agg_grid, 256>>>(b1, st1);

    // ---- GCN layer 2 (messages prescaled by dinv in tgemm2) ----
    tgemm_k<HID, false, false><<<gemm_grid, 256>>>(
        hbuf, bh2, bl2, nullptr, xws, NNODES, HID,
        g1, be1, st1, dinv, nullptr);
    agg_k<false><<<agg_grid, 256>>>(b2, st2);

    // ---- projector linear 1 (stats fused) ----
    tgemm_k<HID, false, true><<<gemm_grid, 256>>>(
        hbuf, bh3, bl3, bp1, xws, NNODES, HID,
        g2, be2, st2, nullptr, st3);

    // ---- projector linear 2 + fused L2 normalize ----
    tgemm_k<PROJ, true, false><<<gemm_grid, 256>>>(
        xws, bh4, bl4, bp2, out, NNODES, HID,
        gp, bep, st3, nullptr, nullptr);
}